// round 17
// baseline (speedup 1.0000x reference)
#include <cuda_runtime.h>
#include <math.h>

// Problem dims
#define BB   64
#define TT   512
#define DIN  64
#define DM   512
#define DOUT 64

// 128 CTAs; 8 row-groups of 8 rows; each CTA serves 2 groups (g, g+4) with the
// same 16 weight columns. 1024 threads.
#define NCTA 128
#define NTHR 1024
#define GR   8    // rows per group
#define CB   16   // h columns per CTA
#define RS8  18   // reduction row stride

// Transposed ping-pong hidden state in global: [k][batch-row], .cg only.
__device__ float g_h0T[2][DM * BB];
__device__ float g_h1T[2][DM * BB];
// Precomputed layer-0 input term: g_pre[cta][t][g2*128 + c*8 + r].
__device__ float g_pre[(size_t)NCTA * TT * 256];
// Epoch-parity flags per group (8 groups x 32 CTAs).
__device__ unsigned g_flags[2][8][32];

struct __align__(16) Smem {
    float  sAT[2][DM][GR];     // h0(t) per group, transposed [k][row]
    float  sBT[2][DM][GR];     // h1(t-1) per group
    float  whh0T[DM][CB];      // weight col-slices [k][col] (shared by groups)
    float  wih1T[DM][CB];
    float  whh1T[DM][CB];
    float  w0s[DIN][CB];       // Wih0 slice (prepass only)
    float2 woutT[DM];          // 2 output columns of Wout
    float  redB[16][GR * RS8]; // layer-1 partials (32 k-groups pair-merged)
    float  redA[16][GR * RS8]; // layer-0 partials
    float2 redo[32][9];        // out-GEMM partials [kgroup][row]
    float  cb0[CB], cb1[CB];
    float2 cbo;
};

__device__ __forceinline__ float ftanh(float x) {
    float e = __expf(2.f * x);
    return 1.f - __fdividef(2.f, e + 1.f);
}

// ---- L2-direct accessors ----
__device__ __forceinline__ float ldcg(const float *p) {
    float v;
    asm volatile("ld.global.cg.f32 %0, [%1];" : "=f"(v) : "l"(p));
    return v;
}
__device__ __forceinline__ void ldcg4(const float *p, float4 &v) {
    asm volatile("ld.global.cg.v4.f32 {%0,%1,%2,%3}, [%4];"
                 : "=f"(v.x), "=f"(v.y), "=f"(v.z), "=f"(v.w)
                 : "l"(p));
}
__device__ __forceinline__ void stcg(float *p, float v) {
    asm volatile("st.global.cg.f32 [%0], %1;" ::"l"(p), "f"(v));
}

// ---- barrier primitives (warp 0 polls only) ----
__device__ __forceinline__ void flag_arrive(unsigned e, int g, int cb) {
    asm volatile("st.release.gpu.u32 [%0], %1;" ::"l"(&g_flags[e & 1u][g][cb]),
                 "r"(e)
                 : "memory");
}
__device__ __forceinline__ void flag_wait(unsigned e, int g, int lane) {
    unsigned v;
    do {
        asm volatile("ld.acquire.gpu.u32 %0, [%1];"
                     : "=r"(v)
                     : "l"(&g_flags[e & 1u][g][lane])
                     : "memory");
    } while (!__all_sync(0xffffffffu, v == e));
}

// ---- packed f32x2 helpers ----
__device__ __forceinline__ unsigned long long pack2(float lo, float hi) {
    unsigned long long r;
    asm("mov.b64 %0, {%1, %2};" : "=l"(r) : "f"(lo), "f"(hi));
    return r;
}
__device__ __forceinline__ void unpack2(unsigned long long v, float &lo, float &hi) {
    asm("mov.b64 {%0, %1}, %2;" : "=f"(lo), "=f"(hi) : "l"(v));
}
__device__ __forceinline__ void fma2(unsigned long long &d, unsigned long long a,
                                     unsigned long long b) {
    asm("fma.rn.f32x2 %0, %1, %2, %0;" : "+l"(d) : "l"(a), "l"(b));
}
__device__ __forceinline__ unsigned long long add2(unsigned long long a,
                                                   unsigned long long b) {
    unsigned long long r;
    asm("add.rn.f32x2 %0, %1, %2;" : "=l"(r) : "l"(a), "l"(b));
    return r;
}

// 2-row x 2-col tile over 8x16 output, 32-way warp-uniform k-split (ks=wid).
// a LDS.64 within one 32B row (1 phase); w LDS.64 within one 64B row (1 phase).
template <bool FUSE>
__device__ __forceinline__ void gemm8(const float *__restrict__ aT,
                                      const float *__restrict__ w1T,
                                      const float *__restrict__ w2T, int ks,
                                      int r2, int c2, unsigned long long accB[2],
                                      unsigned long long accA[2]) {
#pragma unroll
    for (int i = 0; i < 16; i++) {
        int k = i * 32 + ks;
        unsigned long long av = *(const unsigned long long *)&aT[k * GR + r2];
        unsigned long long w1 = *(const unsigned long long *)&w1T[k * CB + c2];
        float ax, ay;
        unpack2(av, ax, ay);
        unsigned long long a0 = pack2(ax, ax);
        unsigned long long a1 = pack2(ay, ay);
        fma2(accB[0], a0, w1);
        fma2(accB[1], a1, w1);
        if (FUSE) {
            unsigned long long w2 = *(const unsigned long long *)&w2T[k * CB + c2];
            fma2(accA[0], a0, w2);
            fma2(accA[1], a1, w2);
        }
    }
}

__device__ __forceinline__ void scatter8(float (*__restrict__ red)[GR * RS8],
                                         unsigned long long acc[2], int slot,
                                         int r2, int c2) {
#pragma unroll
    for (int rr = 0; rr < 2; rr++)
        *(unsigned long long *)&red[slot][(r2 + rr) * RS8 + c2] = acc[rr];
}
__device__ __forceinline__ void merge8(float (*__restrict__ red)[GR * RS8],
                                       unsigned long long acc[2], int slot, int r2,
                                       int c2) {
#pragma unroll
    for (int rr = 0; rr < 2; rr++) {
        unsigned long long *p =
            (unsigned long long *)&red[slot][(r2 + rr) * RS8 + c2];
        *p = add2(*p, acc[rr]);
    }
}

// o < 128: orr = o&7 (row), oc = o>>3 (col). Conflict-free reads; coalesced
// 32B-sector stores to transposed global h.
__device__ __forceinline__ void finalReduce8(const float (*__restrict__ red)[GR * RS8],
                                             float bias, float *__restrict__ gdstT,
                                             int o, int r0g, int c0) {
    int orr = o & 7, oc = o >> 3;
    float s = bias;
#pragma unroll
    for (int j = 0; j < 16; j++) s += red[j][orr * RS8 + oc];
    stcg(&gdstT[(c0 + oc) * BB + r0g + orr], ftanh(s));
}

// Stage 8 rows x 512 k: 1 x (LDG.128.cg + STS.128) per thread per array.
__device__ __forceinline__ void stageH8(float (*__restrict__ dst)[GR],
                                        const float *__restrict__ srcT, int r0g,
                                        int tid) {
    int k = tid >> 1, rg = (tid & 1) << 2;
    float4 v;
    ldcg4(&srcT[k * BB + r0g + rg], v);
    *(float4 *)&dst[k][rg] = v;
}

// out-GEMM: warp wid covers k in [wid*16, wid*16+16); lane: row=lane>>2,
// q=lane&3; k = wid*16 + 4i + q. Bank = 8q + row: conflict-free.
__device__ __forceinline__ void out_partial8(Smem &S, int g2, int wid, int lane) {
    int row = lane >> 2, q = lane & 3;
    unsigned long long o0 = pack2(0.f, 0.f), o1 = pack2(0.f, 0.f);
#pragma unroll
    for (int i = 0; i < 4; i++) {
        int k = wid * 16 + i * 4 + q;
        float av = S.sBT[g2][k][row];
        unsigned long long w = *(const unsigned long long *)&S.woutT[k];
        fma2((i & 1) ? o1 : o0, pack2(av, av), w);
    }
    unsigned long long tot = add2(o0, o1);
    tot = add2(tot, __shfl_xor_sync(0xffffffffu, tot, 1));
    tot = add2(tot, __shfl_xor_sync(0xffffffffu, tot, 2));
    if (q == 0) {
        float x, y;
        unpack2(tot, x, y);
        S.redo[wid][row] = make_float2(x, y);
    }
}

__global__ void __launch_bounds__(NTHR, 1)
rnn_persistent_kernel(const float *__restrict__ data, const float *__restrict__ Wih0,
                      const float *__restrict__ bih0, const float *__restrict__ Whh0,
                      const float *__restrict__ bhh0, const float *__restrict__ Wih1,
                      const float *__restrict__ bih1, const float *__restrict__ Whh1,
                      const float *__restrict__ bhh1, const float *__restrict__ Wout,
                      const float *__restrict__ bout, float *__restrict__ out) {
    extern __shared__ char smem_raw[];
    Smem &S = *reinterpret_cast<Smem *>(smem_raw);

    const int tid = threadIdx.x;
    const int cta = blockIdx.x;
    const int GP = cta >> 5;   // group pair id 0..3 -> groups GP, GP+4
    const int cb = cta & 31;
    const int c0 = cb * CB;
    const int oc0 = cb * 2;
    const int wid = tid >> 5;
    const int lane = tid & 31;
    const int ks = wid;               // 32-way k-split (warp-uniform)
    const int slot = wid & 15;
    const bool writer = (wid < 16);
    const int r2 = (lane >> 3) * 2;   // rows r2, r2+1 (0..7)
    const int c2 = (lane & 7) * 2;    // cols c2, c2+1
    float *preCta = &g_pre[(size_t)cta * TT * 256];

    // ---- one-time: weights -> smem ----
    for (int idx = tid; idx < DM * CB; idx += NTHR) {
        int k = idx >> 4, c = idx & 15;
        S.whh0T[k][c] = Whh0[k * DM + c0 + c];
        S.wih1T[k][c] = Wih1[k * DM + c0 + c];
        S.whh1T[k][c] = Whh1[k * DM + c0 + c];
    }
    {
        int k = tid >> 4, c = tid & 15;  // 1024 = 64*16 exactly
        S.w0s[k][c] = Wih0[k * DM + c0 + c];
    }
    for (int k = tid; k < DM; k += NTHR)
        S.woutT[k] = *(const float2 *)&Wout[k * DOUT + oc0];
    if (tid < CB) {
        S.cb0[tid] = bih0[c0 + tid] + bhh0[c0 + tid];
        S.cb1[tid] = bih1[c0 + tid] + bhh1[c0 + tid];
    }
    if (tid == 0) S.cbo = make_float2(bout[oc0], bout[oc0 + 1]);
    __syncthreads();

    // ---- prepass: pre[t] = x(t)@Wih0 + b0 for both group slices ----
    {
        int r = lane & 7, ch = lane >> 3;  // ch covers cols ch*4..ch*4+3
        for (int i = 0; i < 16; i++) {
            int t = wid * 16 + i;
#pragma unroll
            for (int g2 = 0; g2 < 2; g2++) {
                int r0g = (GP + g2 * 4) * GR;
                const float *xrow = &data[((size_t)(r0g + r) * TT + t) * DIN];
                unsigned long long a0 = pack2(0.f, 0.f), a1 = pack2(0.f, 0.f);
#pragma unroll 4
                for (int kq = 0; kq < 16; kq++) {
                    float4 xv = *(const float4 *)&xrow[kq * 4];
                    float xa[4] = {xv.x, xv.y, xv.z, xv.w};
#pragma unroll
                    for (int j = 0; j < 4; j++) {
                        ulonglong2 wv =
                            *(const ulonglong2 *)&S.w0s[kq * 4 + j][ch * 4];
                        unsigned long long xx = pack2(xa[j], xa[j]);
                        fma2(a0, xx, wv.x);
                        fma2(a1, xx, wv.y);
                    }
                }
                float *dst = preCta + (size_t)t * 256 + g2 * 128;
                float v0, v1, v2, v3;
                unpack2(a0, v0, v1);
                unpack2(a1, v2, v3);
                int c = ch * 4;
                stcg(&dst[c * 8 + r], v0 + S.cb0[c]);
                stcg(&dst[(c + 1) * 8 + r], v1 + S.cb0[c + 1]);
                stcg(&dst[(c + 2) * 8 + r], v2 + S.cb0[c + 2]);
                stcg(&dst[(c + 3) * 8 + r], v3 + S.cb0[c + 3]);
            }
        }
    }
    __syncthreads();

    // ---- prologue: h0(0) = tanh(pre[0]) for both groups ----
    if (tid < 256) {
        int g2 = tid >> 7, o = tid & 127;
        int r0g = (GP + g2 * 4) * GR;
        float p = ldcg(&preCta[g2 * 128 + o]);
        stcg(&g_h0T[0][(c0 + (o >> 3)) * BB + r0g + (o & 7)], ftanh(p));
    }
    __syncthreads();
    if (tid == 0) {
        flag_arrive(1, GP, cb);
        flag_arrive(1, GP + 4, cb);
    }

#pragma unroll 1
    for (int t = 0; t < TT; t++) {
#pragma unroll 1
        for (int g2 = 0; g2 < 2; g2++) {
            const int g = GP + g2 * 4;
            const int r0g = g * GR;
            const unsigned e = (unsigned)t + 1;

            // CTA-private prefetch of pre(t+1) before the wait
            float pf = 0.f;
            if (tid >= 128 && tid < 256) {
                int tn = (t + 1 < TT) ? t + 1 : TT - 1;
                pf = ldcg(&preCta[(size_t)tn * 256 + g2 * 128 + (tid - 128)]);
            }
            // wait for this group's peers (arrived ~one phase ago)
            if (tid < 32) flag_wait(e, g, lane);
            __syncthreads();

            stageH8(S.sAT[g2], g_h0T[t & 1], r0g, tid);
            if (t > 0) stageH8(S.sBT[g2], g_h1T[(t + 1) & 1], r0g, tid);
            __syncthreads();

            unsigned long long accB[2], accA[2];
            accB[0] = accB[1] = accA[0] = accA[1] = pack2(0.f, 0.f);
            // fused: accB += h0(t)@Wih1, accA += h0(t)@Whh0
            gemm8<true>(&S.sAT[g2][0][0], &S.wih1T[0][0], &S.whh0T[0][0], ks, r2,
                        c2, accB, accA);
            if (t > 0) {
                unsigned long long dummy[2];
                gemm8<false>(&S.sBT[g2][0][0], &S.whh1T[0][0], nullptr, ks, r2, c2,
                             accB, dummy);
                out_partial8(S, g2, wid, lane);
            }
            if (writer) {
                scatter8(S.redB, accB, slot, r2, c2);
                scatter8(S.redA, accA, slot, r2, c2);
            }
            __syncthreads();
            if (!writer) {
                merge8(S.redB, accB, slot, r2, c2);
                merge8(S.redA, accA, slot, r2, c2);
            }
            __syncthreads();

            if (tid < 128) {  // h1(t)
                finalReduce8(S.redB, S.cb1[tid >> 3], g_h1T[t & 1], tid, r0g, c0);
            } else if (tid < 256) {  // h0(t+1) (t=511 write is never read)
                finalReduce8(S.redA, pf, g_h0T[(t + 1) & 1], tid - 128, r0g, c0);
            } else if (tid < 264 && t > 0) {  // out(t-1)
                int row = tid - 256;
                float s0 = S.cbo.x, s1 = S.cbo.y;
#pragma unroll
                for (int j = 0; j < 32; j++) {
                    float2 p = S.redo[j][row];
                    s0 += p.x;
                    s1 += p.y;
                }
                *(float2 *)&out[((r0g + row) * TT + (t - 1)) * DOUT + oc0] =
                    make_float2(s0, s1);
            }
            __syncthreads();
            if (tid == 0) flag_arrive(e + 1, g, cb);
        }
    }

    // ---- epilogue: out(T-1) for both groups ----
    if (tid < 32) {
        flag_wait(TT + 1, GP, lane);
        flag_wait(TT + 1, GP + 4, lane);
    }
    __syncthreads();
    stageH8(S.sBT[0], g_h1T[1], GP * GR, tid);
    stageH8(S.sBT[1], g_h1T[1], (GP + 4) * GR, tid);
    __syncthreads();
#pragma unroll 1
    for (int g2 = 0; g2 < 2; g2++) {
        out_partial8(S, g2, wid, lane);
        __syncthreads();
        if (tid < 8) {
            int r0g = (GP + g2 * 4) * GR;
            float s0 = S.cbo.x, s1 = S.cbo.y;
#pragma unroll
            for (int j = 0; j < 32; j++) {
                float2 p = S.redo[j][tid];
                s0 += p.x;
                s1 += p.y;
            }
            *(float2 *)&out[((r0g + tid) * TT + (TT - 1)) * DOUT + oc0] =
                make_float2(s0, s1);
        }
        __syncthreads();
    }
}

extern "C" void kernel_launch(void *const *d_in, const int *in_sizes, int n_in,
                              void *d_out, int out_size) {
    const float *data = (const float *)d_in[0];
    const float *Wih0 = (const float *)d_in[1];
    const float *bih0 = (const float *)d_in[2];
    const float *Whh0 = (const float *)d_in[3];
    const float *bhh0 = (const float *)d_in[4];
    const float *Wih1 = (const float *)d_in[5];
    const float *bih1 = (const float *)d_in[6];
    const float *Whh1 = (const float *)d_in[7];
    const float *bhh1 = (const float *)d_in[8];
    const float *Wout = (const float *)d_in[9];
    const float *bout = (const float *)d_in[10];
    float *out = (float *)d_out;

    cudaFuncSetAttribute(rnn_persistent_kernel,
                         cudaFuncAttributeMaxDynamicSharedMemorySize,
                         (int)sizeof(Smem));

    rnn_persistent_kernel<<<NCTA, NTHR, sizeof(Smem)>>>(
        data, Wih0, bih0, Whh0, bhh0, Wih1, bih1, Whh1, bhh1, Wout, bout, out);
}